// round 12
// baseline (speedup 1.0000x reference)
#include <cuda_runtime.h>

// GRU_83906481094863 — v11: v9 + n-gate ih offloaded to aux + grouped interleave.
// B=512, T=1024, D=46, H=128. 128 CTAs x 192 threads, NB=4 batches/CTA.
//   gate threads (tid<128, 4 warps = 1/SMSP): unit u owns rows {u,u+128,u+256}.
//     hh-dot (smem W, k-chunk-major LDS.128) with r/z ih chunks INTERLEAVED at
//     group granularity (register W_ih filler inside the scheduler window).
//     n-gate ih part read from smem xn (computed one step ahead by aux).
//     12 accums, ~96 wih regs -> headroom for load pipelining.
//   aux threads (tid 128-191, 2 warps): compute xn(t+1) from x(t+1) with the
//     n-gate W_ih rows in registers; prefetch x(t+2). x triple-buffered.
// ONE __syncthreads per step. MUFU nonlinearities, biases folded.

#define BB 512
#define TT 1024
#define DD 46
#define DP 48
#define HH 128
#define GG 384
#define NB 4
#define NCTA (BB/NB) // 128
#define NTHR 192
#define NGATE 128

// Shared floats: sW[49152] | sH[2][NB][HH](1024) | sX[3][NB][DP](576)
//                | sXN[2][NB][HH](1024)
#define OFF_H  49152
#define OFF_X  50176
#define OFF_XN 50752
#define SMEM_FLOATS 51776
#define SMEM_BYTES  (SMEM_FLOATS * 4)   // 207104

__device__ __forceinline__ void fma2(unsigned long long &d,
                                     unsigned long long a,
                                     unsigned long long b) {
    asm("fma.rn.f32x2 %0, %1, %2, %0;" : "+l"(d) : "l"(a), "l"(b));
}
__device__ __forceinline__ float sum2(unsigned long long v) {
    float lo, hi;
    asm("mov.b64 {%0, %1}, %2;" : "=f"(lo), "=f"(hi) : "l"(v));
    return lo + hi;
}
__device__ __forceinline__ unsigned long long pack2(float lo, float hi) {
    unsigned long long v;
    asm("mov.b64 %0, {%1, %2};" : "=l"(v) : "f"(lo), "f"(hi));
    return v;
}
__device__ __forceinline__ float fast_sig(float x) {
    float e = __expf(-x);
    return __fdividef(1.f, 1.f + e);
}
__device__ __forceinline__ float fast_tanh(float x) {
    x = fminf(15.f, fmaxf(-15.f, x));
    float e = __expf(-2.f * x);
    return __fdividef(1.f - e, 1.f + e);
}

// aux: xn[u] = (W_ih x)_n + b_ih,n for units a and a+64, 4 batches
__device__ __forceinline__ void aux_xn(const float* __restrict__ xb,
                                       float* __restrict__ xnOut,
                                       const unsigned long long wn[2][24],
                                       const float bin[2], int a) {
    unsigned long long an[2][NB];
    #pragma unroll
    for (int uu = 0; uu < 2; uu++)
        #pragma unroll
        for (int nb = 0; nb < NB; nb++)
            an[uu][nb] = pack2(bin[uu], 0.f);
    #pragma unroll
    for (int q = 0; q < 12; q++) {
        ulonglong2 xA = *(const ulonglong2*)(xb + 0 * DP + 4 * q);
        ulonglong2 xB = *(const ulonglong2*)(xb + 1 * DP + 4 * q);
        ulonglong2 xC = *(const ulonglong2*)(xb + 2 * DP + 4 * q);
        ulonglong2 xD = *(const ulonglong2*)(xb + 3 * DP + 4 * q);
        #pragma unroll
        for (int uu = 0; uu < 2; uu++) {
            unsigned long long wa = wn[uu][2 * q], wb = wn[uu][2 * q + 1];
            fma2(an[uu][0], wa, xA.x); fma2(an[uu][0], wb, xA.y);
            fma2(an[uu][1], wa, xB.x); fma2(an[uu][1], wb, xB.y);
            fma2(an[uu][2], wa, xC.x); fma2(an[uu][2], wb, xC.y);
            fma2(an[uu][3], wa, xD.x); fma2(an[uu][3], wb, xD.y);
        }
    }
    #pragma unroll
    for (int uu = 0; uu < 2; uu++)
        #pragma unroll
        for (int nb = 0; nb < NB; nb++)
            xnOut[nb * HH + a + uu * 64] = sum2(an[uu][nb]);
}

__global__ void __launch_bounds__(NTHR, 1) gru_v11(
    const float* __restrict__ history,  // [B][T][D]
    const float* __restrict__ W_ih,     // [3H][D]
    const float* __restrict__ W_hh,     // [3H][H]
    const float* __restrict__ b_ih,     // [3H]
    const float* __restrict__ b_hh,     // [3H]
    const float* __restrict__ h0,       // [H]
    float* __restrict__ out)            // [B][H]
{
    extern __shared__ float smem[];
    float* sW  = smem;            // float4 view: (kc*GG + j)
    float* sH  = smem + OFF_H;    // [2][NB][HH]
    float* sX  = smem + OFF_X;    // [3][NB][DP]
    float* sXN = smem + OFF_XN;   // [2][NB][HH]

    const int tid = threadIdx.x;
    const int b0  = blockIdx.x * NB;

    // ---- stage W_hh k-chunk-major ----
    for (int idx = tid; idx < GG * HH; idx += NTHR) {
        int j = idx >> 7, k = idx & 127;
        sW[((k >> 2) * GG + j) * 4 + (k & 3)] = W_hh[idx];
    }
    // ---- h(0) ----
    for (int idx = tid; idx < NB * HH; idx += NTHR)
        sH[idx] = h0[idx & 127];
    // ---- zero x pads (3 buffers) ----
    if (tid < 24) {
        int buf = tid >> 3, nb = (tid >> 1) & 3, d = DD + (tid & 1);
        sX[buf * (NB * DP) + nb * DP + d] = 0.f;
    }
    // ---- x(0)->buf0, x(1)->buf1 ----
    for (int idx = tid; idx < NB * DD; idx += NTHR) {
        int nb = idx / DD, d = idx - nb * DD;
        sX[nb * DP + d]            = history[(size_t)(b0 + nb) * (TT * DD) + d];
        sX[NB * DP + nb * DP + d]  = history[(size_t)(b0 + nb) * (TT * DD) + DD + d];
    }

    // ---- per-role private state ----
    const bool is_gate = (tid < NGATE);
    const int  u = tid;                  // gate unit
    const int  a = tid - NGATE;          // aux lane 0..63
    unsigned long long wih[2][24];       // gate: r/z rows
    unsigned long long wn[2][24];        // aux: n rows for units a, a+64
    float brz0 = 0.f, brz1 = 0.f, bhn = 0.f;
    float bin[2] = {0.f, 0.f};
    float hold[NB] = {0.f, 0.f, 0.f, 0.f};
    if (is_gate) {
        brz0 = b_ih[u] + b_hh[u];
        brz1 = b_ih[u + HH] + b_hh[u + HH];
        bhn  = b_hh[u + 2 * HH];
        float h0v = h0[u];
        #pragma unroll
        for (int nb = 0; nb < NB; nb++) hold[nb] = h0v;
        #pragma unroll
        for (int g = 0; g < 2; g++) {
            const int j = u + g * HH;
            #pragma unroll
            for (int p = 0; p < 23; p++)
                wih[g][p] = pack2(W_ih[j * DD + 2 * p], W_ih[j * DD + 2 * p + 1]);
            wih[g][23] = 0ull;
        }
    } else {
        #pragma unroll
        for (int uu = 0; uu < 2; uu++) {
            const int j = 2 * HH + a + uu * 64;
            bin[uu] = b_ih[j];
            #pragma unroll
            for (int p = 0; p < 23; p++)
                wn[uu][p] = pack2(W_ih[j * DD + 2 * p], W_ih[j * DD + 2 * p + 1]);
            wn[uu][23] = 0ull;
        }
    }
    const ulonglong2* wrow0 = (const ulonglong2*)sW + u;   // row u
    const ulonglong2* wrow1 = wrow0 + HH;                  // row u+128
    const ulonglong2* wrow2 = wrow0 + 2 * HH;              // row u+256

    __syncthreads();

    // pre-step: aux computes xn(0) from x buf0
    if (!is_gate)
        aux_xn(sX, sXN, wn, bin, a);
    __syncthreads();

    // x rotating buffer indices: i0 = t%3 (x(t)), i1 (x(t+1)), i2 (x(t+2) dst)
    int i0 = 0, i1 = 1, i2 = 2;

    for (int t = 0; t < TT; t++) {
        const int cur = t & 1, nxt = cur ^ 1;

        if (is_gate) {
            const float* hb = sH + cur * (NB * HH);
            const float* xb = sX + i0 * (NB * DP);

            // a0: r total, a1: z total, a2: g_n (hh only); biases folded.
            unsigned long long a0[NB], a1[NB], a2[NB];
            #pragma unroll
            for (int nb = 0; nb < NB; nb++) {
                a0[nb] = pack2(brz0, 0.f);
                a1[nb] = pack2(brz1, 0.f);
                a2[nb] = pack2(bhn, 0.f);
            }

            // ---- grouped interleave: 8 x (4 hh chunks [+2 r/z ih chunks]) ----
            #pragma unroll
            for (int grp = 0; grp < 8; grp++) {
                #pragma unroll
                for (int s = 0; s < 4; s++) {
                    const int kc = grp * 4 + s;
                    ulonglong2 w0 = wrow0[kc * GG];
                    ulonglong2 w1 = wrow1[kc * GG];
                    ulonglong2 w2 = wrow2[kc * GG];
                    ulonglong2 hA = *(const ulonglong2*)(hb + 0 * HH + kc * 4);
                    ulonglong2 hB = *(const ulonglong2*)(hb + 1 * HH + kc * 4);
                    ulonglong2 hC = *(const ulonglong2*)(hb + 2 * HH + kc * 4);
                    ulonglong2 hD = *(const ulonglong2*)(hb + 3 * HH + kc * 4);
                    fma2(a0[0], w0.x, hA.x); fma2(a0[0], w0.y, hA.y);
                    fma2(a0[1], w0.x, hB.x); fma2(a0[1], w0.y, hB.y);
                    fma2(a0[2], w0.x, hC.x); fma2(a0[2], w0.y, hC.y);
                    fma2(a0[3], w0.x, hD.x); fma2(a0[3], w0.y, hD.y);
                    fma2(a1[0], w1.x, hA.x); fma2(a1[0], w1.y, hA.y);
                    fma2(a1[1], w1.x, hB.x); fma2(a1[1], w1.y, hB.y);
                    fma2(a1[2], w1.x, hC.x); fma2(a1[2], w1.y, hC.y);
                    fma2(a1[3], w1.x, hD.x); fma2(a1[3], w1.y, hD.y);
                    fma2(a2[0], w2.x, hA.x); fma2(a2[0], w2.y, hA.y);
                    fma2(a2[1], w2.x, hB.x); fma2(a2[1], w2.y, hB.y);
                    fma2(a2[2], w2.x, hC.x); fma2(a2[2], w2.y, hC.y);
                    fma2(a2[3], w2.x, hD.x); fma2(a2[3], w2.y, hD.y);
                }
                if (grp < 6) {
                    #pragma unroll
                    for (int e = 0; e < 2; e++) {
                        const int q = grp * 2 + e;
                        ulonglong2 xA = *(const ulonglong2*)(xb + 0 * DP + 4 * q);
                        ulonglong2 xB = *(const ulonglong2*)(xb + 1 * DP + 4 * q);
                        ulonglong2 xC = *(const ulonglong2*)(xb + 2 * DP + 4 * q);
                        ulonglong2 xD = *(const ulonglong2*)(xb + 3 * DP + 4 * q);
                        unsigned long long w0a = wih[0][2*q], w0b = wih[0][2*q+1];
                        unsigned long long w1a = wih[1][2*q], w1b = wih[1][2*q+1];
                        fma2(a0[0], w0a, xA.x); fma2(a0[0], w0b, xA.y);
                        fma2(a0[1], w0a, xB.x); fma2(a0[1], w0b, xB.y);
                        fma2(a0[2], w0a, xC.x); fma2(a0[2], w0b, xC.y);
                        fma2(a0[3], w0a, xD.x); fma2(a0[3], w0b, xD.y);
                        fma2(a1[0], w1a, xA.x); fma2(a1[0], w1b, xA.y);
                        fma2(a1[1], w1a, xB.x); fma2(a1[1], w1b, xB.y);
                        fma2(a1[2], w1a, xC.x); fma2(a1[2], w1b, xC.y);
                        fma2(a1[3], w1a, xD.x); fma2(a1[3], w1b, xD.y);
                    }
                }
            }

            // ---- nonlinearity + h update (xn from smem, h carried in regs) ----
            const float* xnb = sXN + cur * (NB * HH);
            float* hn = sH + nxt * (NB * HH);
            #pragma unroll
            for (int nb = 0; nb < NB; nb++) {
                float r = fast_sig(sum2(a0[nb]));
                float z = fast_sig(sum2(a1[nb]));
                float n = fast_tanh(xnb[nb * HH + u] + r * sum2(a2[nb]));
                float hv = n + z * (hold[nb] - n);
                hold[nb] = hv;
                hn[nb * HH + u] = hv;
                if (t == TT - 1)
                    out[(size_t)(b0 + nb) * HH + u] = hv;
            }
        } else {
            // ---- aux: prefetch x(t+2) into buf i2; xn(t+1) from x(t+1) ----
            if (t + 2 < TT) {
                #pragma unroll
                for (int r = 0; r < 3; r++) {
                    int idx = a + r * 64;
                    if (idx < NB * DD) {
                        int nb = idx / DD, d = idx - nb * DD;
                        sX[i2 * (NB * DP) + nb * DP + d] =
                            history[(size_t)(b0 + nb) * (TT * DD) + (t + 2) * DD + d];
                    }
                }
            }
            if (t + 1 < TT)
                aux_xn(sX + i1 * (NB * DP), sXN + nxt * (NB * HH), wn, bin, a);
        }

        __syncthreads();   // h(t+1), xn(t+1), x(t+2) published

        int tmp = i0; i0 = i1; i1 = i2; i2 = tmp;
    }
}

extern "C" void kernel_launch(void* const* d_in, const int* in_sizes, int n_in,
                              void* d_out, int out_size) {
    const float* history = (const float*)d_in[0];
    const float* W_ih    = (const float*)d_in[1];
    const float* W_hh    = (const float*)d_in[2];
    const float* b_ih    = (const float*)d_in[3];
    const float* b_hh    = (const float*)d_in[4];
    const float* h0      = (const float*)d_in[5];
    float* out = (float*)d_out;

    cudaFuncSetAttribute(gru_v11,
                         cudaFuncAttributeMaxDynamicSharedMemorySize, SMEM_BYTES);
    gru_v11<<<NCTA, NTHR, SMEM_BYTES>>>(history, W_ih, W_hh,
                                        b_ih, b_hh, h0, out);
}

// round 13
// speedup vs baseline: 1.0787x; 1.0787x over previous
#include <cuda_runtime.h>

// GRU_83906481094863 — v12: warp-level k-split, smem combine (sm_100a).
// B=512, T=1024, D=46, H=128. 128 CTAs x 512 threads, NB=4 batches/CTA.
// 16 gate warps (4/SMSP): warp w -> k-quarter kq=w>>2, units (w&3)*32+lane.
//   Phase A (all warps): partial dots of rows {u,u+128,u+256} over k-quarter
//     (W from smem k-chunk-major LDS.128, h/x broadcast reads of ONLY the
//     quarter -> h traffic stays at the 4-warp minimum, 512 wf/step);
//     partials (r,z,gn,xn) x 4 batches -> smem sP.  barrier.
//   Phase B: warps 0-3 combine partials + MUFU nonlinearity + h update
//     (h carried in regs, written to single-buffer sH); warps 4-7 prefetch
//     x(t+1) into single-buffer sX.  barrier.
// Biases folded into kq==0 partial init. W_ih quarter-rows in registers.

#define BB 512
#define TT 1024
#define DD 46
#define DP 48
#define HH 128
#define GG 384
#define NB 4
#define NCTA (BB/NB)   // 128
#define NTHR 512

// Shared floats:
//  sW [0, 49152)        W_hh k-chunk-major: float4 idx (kc*GG + j)
//  sP [49152, 57344)    partials [4 kq][NB][4 comp][128 u]  (c:0=r,1=z,2=gn,3=xn)
//  sH [57344, 57856)    h single buffer [NB][HH]
//  sX [57856, 58048)    x single buffer [NB][DP]
#define OFF_P 49152
#define OFF_H 57344
#define OFF_X 57856
#define SMEM_FLOATS 58048
#define SMEM_BYTES  (SMEM_FLOATS * 4)   // 232192 <= 232448 cap

__device__ __forceinline__ void fma2(unsigned long long &d,
                                     unsigned long long a,
                                     unsigned long long b) {
    asm("fma.rn.f32x2 %0, %1, %2, %0;" : "+l"(d) : "l"(a), "l"(b));
}
__device__ __forceinline__ float sum2(unsigned long long v) {
    float lo, hi;
    asm("mov.b64 {%0, %1}, %2;" : "=f"(lo), "=f"(hi) : "l"(v));
    return lo + hi;
}
__device__ __forceinline__ unsigned long long pack2(float lo, float hi) {
    unsigned long long v;
    asm("mov.b64 %0, {%1, %2};" : "=l"(v) : "f"(lo), "f"(hi));
    return v;
}
__device__ __forceinline__ float fast_sig(float x) {
    float e = __expf(-x);
    return __fdividef(1.f, 1.f + e);
}
__device__ __forceinline__ float fast_tanh(float x) {
    x = fminf(15.f, fmaxf(-15.f, x));
    float e = __expf(-2.f * x);
    return __fdividef(1.f - e, 1.f + e);
}

__global__ void __launch_bounds__(NTHR, 1) gru_v12(
    const float* __restrict__ history,  // [B][T][D]
    const float* __restrict__ W_ih,     // [3H][D]
    const float* __restrict__ W_hh,     // [3H][H]
    const float* __restrict__ b_ih,     // [3H]
    const float* __restrict__ b_hh,     // [3H]
    const float* __restrict__ h0,       // [H]
    float* __restrict__ out)            // [B][H]
{
    extern __shared__ float smem[];
    float* sW = smem;
    float* sP = smem + OFF_P;    // [4][NB][4][128]
    float* sH = smem + OFF_H;    // [NB][HH]
    float* sX = smem + OFF_X;    // [NB][DP]

    const int tid  = threadIdx.x;
    const int b0   = blockIdx.x * NB;
    const int lane = tid & 31;
    const int wid  = tid >> 5;
    const int kq   = wid >> 2;              // k-quarter 0..3
    const int uc   = ((wid & 3) << 5) + lane;  // compute unit 0..127

    // ---- stage W_hh k-chunk-major ----
    for (int idx = tid; idx < GG * HH; idx += NTHR) {
        int j = idx >> 7, k = idx & 127;
        sW[((k >> 2) * GG + j) * 4 + (k & 3)] = W_hh[idx];
    }
    // ---- h(0) ----
    for (int idx = tid; idx < NB * HH; idx += NTHR)
        sH[idx] = h0[idx & 127];
    // ---- zero x pads; x(0) ----
    if (tid < 8) {
        int nb = tid >> 1, d = DD + (tid & 1);
        sX[nb * DP + d] = 0.f;
    }
    for (int idx = tid; idx < NB * DD; idx += NTHR) {
        int nb = idx / DD, d = idx - nb * DD;
        sX[nb * DP + d] = history[(size_t)(b0 + nb) * (TT * DD) + d];
    }

    // ---- per-thread W_ih quarter-rows (12 k each; pads zero) + biases ----
    unsigned long long wih[3][6];
    float binit[4] = {0.f, 0.f, 0.f, 0.f};   // kq==0 partial init (r,z,gn,xn)
    #pragma unroll
    for (int g = 0; g < 3; g++) {
        const int j = g * HH + uc;
        #pragma unroll
        for (int p = 0; p < 6; p++) {
            int k0 = kq * 12 + 2 * p;
            float f0 = (k0     < DD) ? W_ih[j * DD + k0]     : 0.f;
            float f1 = (k0 + 1 < DD) ? W_ih[j * DD + k0 + 1] : 0.f;
            wih[g][p] = pack2(f0, f1);
        }
    }
    if (kq == 0) {
        binit[0] = b_ih[uc] + b_hh[uc];
        binit[1] = b_ih[uc + HH] + b_hh[uc + HH];
        binit[2] = b_hh[uc + 2 * HH];
        binit[3] = b_ih[uc + 2 * HH];
    }
    // finisher state (warps 0-3): unit uf = tid, h carried in registers
    const int uf = tid;
    float hold[NB] = {0.f, 0.f, 0.f, 0.f};
    if (tid < HH) {
        float h0v = h0[uf];
        #pragma unroll
        for (int nb = 0; nb < NB; nb++) hold[nb] = h0v;
    }

    const ulonglong2* wr0 = (const ulonglong2*)sW + (kq * 8) * GG + uc;
    const ulonglong2* wr1 = wr0 + HH;
    const ulonglong2* wr2 = wr0 + 2 * HH;
    const float* hq = sH + kq * 32;       // quarter base within a batch row
    const float* xq = sX + kq * 12;
    float* pOut = sP + kq * 2048 + uc;    // + nb*512 + c*128

    __syncthreads();

    for (int t = 0; t < TT; t++) {
        // ================= phase A: partial dots =================
        {
            unsigned long long a0[NB], a1[NB], a2[NB], an[NB];
            #pragma unroll
            for (int nb = 0; nb < NB; nb++) {
                a0[nb] = pack2(binit[0], 0.f);
                a1[nb] = pack2(binit[1], 0.f);
                a2[nb] = pack2(binit[2], 0.f);
                an[nb] = pack2(binit[3], 0.f);
            }
            // hh quarter: 8 k-chunks
            #pragma unroll
            for (int i = 0; i < 8; i++) {
                ulonglong2 w0 = wr0[i * GG];
                ulonglong2 w1 = wr1[i * GG];
                ulonglong2 w2 = wr2[i * GG];
                ulonglong2 hA = *(const ulonglong2*)(hq + 0 * HH + i * 4);
                ulonglong2 hB = *(const ulonglong2*)(hq + 1 * HH + i * 4);
                ulonglong2 hC = *(const ulonglong2*)(hq + 2 * HH + i * 4);
                ulonglong2 hD = *(const ulonglong2*)(hq + 3 * HH + i * 4);
                fma2(a0[0], w0.x, hA.x); fma2(a0[0], w0.y, hA.y);
                fma2(a0[1], w0.x, hB.x); fma2(a0[1], w0.y, hB.y);
                fma2(a0[2], w0.x, hC.x); fma2(a0[2], w0.y, hC.y);
                fma2(a0[3], w0.x, hD.x); fma2(a0[3], w0.y, hD.y);
                fma2(a1[0], w1.x, hA.x); fma2(a1[0], w1.y, hA.y);
                fma2(a1[1], w1.x, hB.x); fma2(a1[1], w1.y, hB.y);
                fma2(a1[2], w1.x, hC.x); fma2(a1[2], w1.y, hC.y);
                fma2(a1[3], w1.x, hD.x); fma2(a1[3], w1.y, hD.y);
                fma2(a2[0], w2.x, hA.x); fma2(a2[0], w2.y, hA.y);
                fma2(a2[1], w2.x, hB.x); fma2(a2[1], w2.y, hB.y);
                fma2(a2[2], w2.x, hC.x); fma2(a2[2], w2.y, hC.y);
                fma2(a2[3], w2.x, hD.x); fma2(a2[3], w2.y, hD.y);
            }
            // ih quarter: 3 x-chunks (r/z merge into a0/a1, n into an)
            #pragma unroll
            for (int q = 0; q < 3; q++) {
                ulonglong2 xA = *(const ulonglong2*)(xq + 0 * DP + 4 * q);
                ulonglong2 xB = *(const ulonglong2*)(xq + 1 * DP + 4 * q);
                ulonglong2 xC = *(const ulonglong2*)(xq + 2 * DP + 4 * q);
                ulonglong2 xD = *(const ulonglong2*)(xq + 3 * DP + 4 * q);
                unsigned long long w0a = wih[0][2*q], w0b = wih[0][2*q+1];
                unsigned long long w1a = wih[1][2*q], w1b = wih[1][2*q+1];
                unsigned long long w2a = wih[2][2*q], w2b = wih[2][2*q+1];
                fma2(a0[0], w0a, xA.x); fma2(a0[0], w0b, xA.y);
                fma2(a0[1], w0a, xB.x); fma2(a0[1], w0b, xB.y);
                fma2(a0[2], w0a, xC.x); fma2(a0[2], w0b, xC.y);
                fma2(a0[3], w0a, xD.x); fma2(a0[3], w0b, xD.y);
                fma2(a1[0], w1a, xA.x); fma2(a1[0], w1b, xA.y);
                fma2(a1[1], w1a, xB.x); fma2(a1[1], w1b, xB.y);
                fma2(a1[2], w1a, xC.x); fma2(a1[2], w1b, xC.y);
                fma2(a1[3], w1a, xD.x); fma2(a1[3], w1b, xD.y);
                fma2(an[0], w2a, xA.x); fma2(an[0], w2b, xA.y);
                fma2(an[1], w2a, xB.x); fma2(an[1], w2b, xB.y);
                fma2(an[2], w2a, xC.x); fma2(an[2], w2b, xC.y);
                fma2(an[3], w2a, xD.x); fma2(an[3], w2b, xD.y);
            }
            // write partials (coalesced STS.32)
            #pragma unroll
            for (int nb = 0; nb < NB; nb++) {
                pOut[nb * 512 + 0 * 128] = sum2(a0[nb]);
                pOut[nb * 512 + 1 * 128] = sum2(a1[nb]);
                pOut[nb * 512 + 2 * 128] = sum2(a2[nb]);
                pOut[nb * 512 + 3 * 128] = sum2(an[nb]);
            }
        }

        __syncthreads();   // partials visible; x(t) consumed

        // ================= phase B =================
        if (tid < HH) {
            // finisher: combine 4 kq-partials, nonlinearity, h update
            #pragma unroll
            for (int nb = 0; nb < NB; nb++) {
                const float* p = sP + nb * 512 + uf;
                float pr  = p[0*128] + p[2048 + 0*128] + p[4096 + 0*128] + p[6144 + 0*128];
                float pz  = p[1*128] + p[2048 + 1*128] + p[4096 + 1*128] + p[6144 + 1*128];
                float pgn = p[2*128] + p[2048 + 2*128] + p[4096 + 2*128] + p[6144 + 2*128];
                float pxn = p[3*128] + p[2048 + 3*128] + p[4096 + 3*128] + p[6144 + 3*128];
                float r = fast_sig(pr);
                float z = fast_sig(pz);
                float n = fast_tanh(pxn + r * pgn);
                float hv = n + z * (hold[nb] - n);
                hold[nb] = hv;
                sH[nb * HH + uf] = hv;
                if (t == TT - 1)
                    out[(size_t)(b0 + nb) * HH + uf] = hv;
            }
        } else if (tid < 256) {
            // warps 4-7: prefetch x(t+1) into the single x buffer
            if (t + 1 < TT) {
                const int a = tid - 128;   // 0..127
                #pragma unroll
                for (int r = 0; r < 2; r++) {
                    int idx = a + r * 128;
                    if (idx < NB * DD) {
                        int nb = idx / DD, d = idx - nb * DD;
                        sX[nb * DP + d] =
                            history[(size_t)(b0 + nb) * (TT * DD) + (t + 1) * DD + d];
                    }
                }
            }
        }

        __syncthreads();   // h(t+1), x(t+1) published
    }
}

extern "C" void kernel_launch(void* const* d_in, const int* in_sizes, int n_in,
                              void* d_out, int out_size) {
    const float* history = (const float*)d_in[0];
    const float* W_ih    = (const float*)d_in[1];
    const float* W_hh    = (const float*)d_in[2];
    const float* b_ih    = (const float*)d_in[3];
    const float* b_hh    = (const float*)d_in[4];
    const float* h0      = (const float*)d_in[5];
    float* out = (float*)d_out;

    cudaFuncSetAttribute(gru_v12,
                         cudaFuncAttributeMaxDynamicSharedMemorySize, SMEM_BYTES);
    gru_v12<<<NCTA, NTHR, SMEM_BYTES>>>(history, W_ih, W_hh,
                                        b_ih, b_hh, h0, out);
}

// round 14
// speedup vs baseline: 1.2987x; 1.2040x over previous
#include <cuda_runtime.h>

// GRU_83906481094863 — v13 = v9 + explicit 1-chunk software pipeline.
// B=512, T=1024, D=46, H=128. 128 CTAs x 192 threads, NB=4 batches/CTA.
//   gate threads (tid<128, 4 warps = 1/SMSP): unit u owns rows {u,u+128,u+256}.
//     hh loop manually pipelined: chunk kc+1's W rows + h broadcast loaded
//     while chunk kc's 24 fma2 issue (v9's 250-reg ceiling blocked ptxas from
//     doing this; funded by moving the n-gate W_ih rows to smem, staged
//     k-chunk-major so lane reads are coalesced float4s).
//     ih tail: one 12-chunk loop, r/z from register W_ih + n from smem W_ih.
//   aux threads (tid 128-191): prefetch x(t+1). ONE __syncthreads per step.
// MUFU nonlinearities; r/z biases folded into accumulator init.

#define BB 512
#define TT 1024
#define DD 46
#define DP 48
#define HH 128
#define GG 384
#define NB 4
#define NCTA (BB/NB) // 128
#define NTHR 192
#define NGATE 128

// Shared floats: sW[49152] W_hh k-chunk-major | sWin[6144] n-gate W_ih staged
//                | sH[2][NB][HH](1024) | sX[2][NB][DP](384)
#define OFF_WIN 49152
#define OFF_H   55296
#define OFF_X   56320
#define SMEM_FLOATS 56704
#define SMEM_BYTES  (SMEM_FLOATS * 4)   // 226816

__device__ __forceinline__ void fma2(unsigned long long &d,
                                     unsigned long long a,
                                     unsigned long long b) {
    asm("fma.rn.f32x2 %0, %1, %2, %0;" : "+l"(d) : "l"(a), "l"(b));
}
__device__ __forceinline__ float sum2(unsigned long long v) {
    float lo, hi;
    asm("mov.b64 {%0, %1}, %2;" : "=f"(lo), "=f"(hi) : "l"(v));
    return lo + hi;
}
__device__ __forceinline__ unsigned long long pack2(float lo, float hi) {
    unsigned long long v;
    asm("mov.b64 %0, {%1, %2};" : "=l"(v) : "f"(lo), "f"(hi));
    return v;
}
__device__ __forceinline__ float fast_sig(float x) {
    float e = __expf(-x);
    return __fdividef(1.f, 1.f + e);
}
__device__ __forceinline__ float fast_tanh(float x) {
    x = fminf(15.f, fmaxf(-15.f, x));
    float e = __expf(-2.f * x);
    return __fdividef(1.f - e, 1.f + e);
}

__global__ void __launch_bounds__(NTHR, 1) gru_v13(
    const float* __restrict__ history,  // [B][T][D]
    const float* __restrict__ W_ih,     // [3H][D]
    const float* __restrict__ W_hh,     // [3H][H]
    const float* __restrict__ b_ih,     // [3H]
    const float* __restrict__ b_hh,     // [3H]
    const float* __restrict__ h0,       // [H]
    float* __restrict__ out)            // [B][H]
{
    extern __shared__ float smem[];
    float* sW   = smem;              // float4 view: (kc*GG + j)
    float* sWin = smem + OFF_WIN;    // float4 view: (q*HH + u), n-gate W_ih
    float* sH   = smem + OFF_H;      // [2][NB][HH]
    float* sX   = smem + OFF_X;      // [2][NB][DP]

    const int tid = threadIdx.x;
    const int b0  = blockIdx.x * NB;

    // ---- stage W_hh k-chunk-major ----
    for (int idx = tid; idx < GG * HH; idx += NTHR) {
        int j = idx >> 7, k = idx & 127;
        sW[((k >> 2) * GG + j) * 4 + (k & 3)] = W_hh[idx];
    }
    // ---- stage n-gate W_ih k-chunk-major (pads k=46,47 zero) ----
    for (int idx = tid; idx < HH * DP; idx += NTHR) {
        int u = idx / DP, k = idx - u * DP;
        float v = (k < DD) ? W_ih[(2 * HH + u) * DD + k] : 0.f;
        sWin[((k >> 2) * HH + u) * 4 + (k & 3)] = v;
    }
    // ---- h(0) ----
    for (int idx = tid; idx < NB * HH; idx += NTHR)
        sH[idx] = h0[idx & 127];
    // ---- zero x pads ----
    if (tid < 16) {
        int buf = tid >> 3, nb = (tid >> 1) & 3, d = DD + (tid & 1);
        sX[buf * (NB * DP) + nb * DP + d] = 0.f;
    }
    // ---- x(0) ----
    for (int idx = tid; idx < NB * DD; idx += NTHR) {
        int nb = idx / DD, d = idx - nb * DD;
        sX[nb * DP + d] = history[(size_t)(b0 + nb) * (TT * DD) + d];
    }

    // ---- gate-thread private state (r/z W_ih rows only) ----
    const int u = tid;
    unsigned long long wih[2][24];
    float brz0 = 0.f, brz1 = 0.f, bhn = 0.f, bin = 0.f;
    if (tid < NGATE) {
        brz0 = b_ih[u] + b_hh[u];
        brz1 = b_ih[u + HH] + b_hh[u + HH];
        bhn  = b_hh[u + 2 * HH];
        bin  = b_ih[u + 2 * HH];
        #pragma unroll
        for (int g = 0; g < 2; g++) {
            const int j = u + g * HH;
            #pragma unroll
            for (int p = 0; p < 23; p++)
                wih[g][p] = pack2(W_ih[j * DD + 2 * p], W_ih[j * DD + 2 * p + 1]);
            wih[g][23] = 0ull;
        }
    }
    const ulonglong2* wrow0 = (const ulonglong2*)sW + u;      // row u
    const ulonglong2* wrow1 = wrow0 + HH;                     // row u+128
    const ulonglong2* wrow2 = wrow0 + 2 * HH;                 // row u+256
    const ulonglong2* winrow = (const ulonglong2*)sWin + u;   // n-gate ih row

    __syncthreads();

    for (int t = 0; t < TT; t++) {
        const int cur = t & 1, nxt = cur ^ 1;

        if (tid < NGATE) {
            const float* hb = sH + cur * (NB * HH);
            const float* xb = sX + cur * (NB * DP);

            unsigned long long a0[NB], a1[NB], a2[NB], an[NB];
            #pragma unroll
            for (int nb = 0; nb < NB; nb++) {
                a0[nb] = pack2(brz0, 0.f);
                a1[nb] = pack2(brz1, 0.f);
                a2[nb] = pack2(bhn, 0.f);
                an[nb] = pack2(bin, 0.f);
            }

            // ---- hh-dot, software-pipelined: prefetch chunk kc+1 while
            //      FMAing chunk kc ----
            ulonglong2 w0 = wrow0[0];
            ulonglong2 w1 = wrow1[0];
            ulonglong2 w2 = wrow2[0];
            ulonglong2 hA = *(const ulonglong2*)(hb + 0 * HH);
            ulonglong2 hB = *(const ulonglong2*)(hb + 1 * HH);
            ulonglong2 hC = *(const ulonglong2*)(hb + 2 * HH);
            ulonglong2 hD = *(const ulonglong2*)(hb + 3 * HH);
            #pragma unroll 8
            for (int kc = 0; kc < 32; kc++) {
                ulonglong2 cw0 = w0, cw1 = w1, cw2 = w2;
                ulonglong2 chA = hA, chB = hB, chC = hC, chD = hD;
                if (kc < 31) {
                    w0 = wrow0[(kc + 1) * GG];
                    w1 = wrow1[(kc + 1) * GG];
                    w2 = wrow2[(kc + 1) * GG];
                    hA = *(const ulonglong2*)(hb + 0 * HH + (kc + 1) * 4);
                    hB = *(const ulonglong2*)(hb + 1 * HH + (kc + 1) * 4);
                    hC = *(const ulonglong2*)(hb + 2 * HH + (kc + 1) * 4);
                    hD = *(const ulonglong2*)(hb + 3 * HH + (kc + 1) * 4);
                }
                fma2(a0[0], cw0.x, chA.x); fma2(a0[0], cw0.y, chA.y);
                fma2(a0[1], cw0.x, chB.x); fma2(a0[1], cw0.y, chB.y);
                fma2(a0[2], cw0.x, chC.x); fma2(a0[2], cw0.y, chC.y);
                fma2(a0[3], cw0.x, chD.x); fma2(a0[3], cw0.y, chD.y);
                fma2(a1[0], cw1.x, chA.x); fma2(a1[0], cw1.y, chA.y);
                fma2(a1[1], cw1.x, chB.x); fma2(a1[1], cw1.y, chB.y);
                fma2(a1[2], cw1.x, chC.x); fma2(a1[2], cw1.y, chC.y);
                fma2(a1[3], cw1.x, chD.x); fma2(a1[3], cw1.y, chD.y);
                fma2(a2[0], cw2.x, chA.x); fma2(a2[0], cw2.y, chA.y);
                fma2(a2[1], cw2.x, chB.x); fma2(a2[1], cw2.y, chB.y);
                fma2(a2[2], cw2.x, chC.x); fma2(a2[2], cw2.y, chC.y);
                fma2(a2[3], cw2.x, chD.x); fma2(a2[3], cw2.y, chD.y);
            }

            // ---- ih-dot: r/z from register W, n from smem W (one loop) ----
            #pragma unroll
            for (int q = 0; q < 12; q++) {
                ulonglong2 wn = winrow[q * HH];
                ulonglong2 xA = *(const ulonglong2*)(xb + 0 * DP + 4 * q);
                ulonglong2 xB = *(const ulonglong2*)(xb + 1 * DP + 4 * q);
                ulonglong2 xC = *(const ulonglong2*)(xb + 2 * DP + 4 * q);
                ulonglong2 xD = *(const ulonglong2*)(xb + 3 * DP + 4 * q);
                unsigned long long w0a = wih[0][2*q], w0b = wih[0][2*q+1];
                unsigned long long w1a = wih[1][2*q], w1b = wih[1][2*q+1];
                fma2(a0[0], w0a, xA.x); fma2(a0[0], w0b, xA.y);
                fma2(a0[1], w0a, xB.x); fma2(a0[1], w0b, xB.y);
                fma2(a0[2], w0a, xC.x); fma2(a0[2], w0b, xC.y);
                fma2(a0[3], w0a, xD.x); fma2(a0[3], w0b, xD.y);
                fma2(a1[0], w1a, xA.x); fma2(a1[0], w1b, xA.y);
                fma2(a1[1], w1a, xB.x); fma2(a1[1], w1b, xB.y);
                fma2(a1[2], w1a, xC.x); fma2(a1[2], w1b, xC.y);
                fma2(a1[3], w1a, xD.x); fma2(a1[3], w1b, xD.y);
                fma2(an[0], wn.x, xA.x); fma2(an[0], wn.y, xA.y);
                fma2(an[1], wn.x, xB.x); fma2(an[1], wn.y, xB.y);
                fma2(an[2], wn.x, xC.x); fma2(an[2], wn.y, xC.y);
                fma2(an[3], wn.x, xD.x); fma2(an[3], wn.y, xD.y);
            }

            // ---- nonlinearity + h update (MUFU) ----
            float* hn = sH + nxt * (NB * HH);
            #pragma unroll
            for (int nb = 0; nb < NB; nb++) {
                float r = fast_sig(sum2(a0[nb]));
                float z = fast_sig(sum2(a1[nb]));
                float n = fast_tanh(sum2(an[nb]) + r * sum2(a2[nb]));
                float hold = hb[nb * HH + u];
                float hv = n + z * (hold - n);
                hn[nb * HH + u] = hv;
                if (t == TT - 1)
                    out[(size_t)(b0 + nb) * HH + u] = hv;
            }
        } else {
            // ---- aux: prefetch x(t+1) ----
            if (t + 1 < TT) {
                const int a = tid - NGATE;   // 0..63
                #pragma unroll
                for (int r = 0; r < 3; r++) {
                    int idx = a + r * 64;
                    if (idx < NB * DD) {
                        int nb = idx / DD, d = idx - nb * DD;
                        sX[nxt * (NB * DP) + nb * DP + d] =
                            history[(size_t)(b0 + nb) * (TT * DD) + (t + 1) * DD + d];
                    }
                }
            }
        }

        __syncthreads();   // h(t+1) + x(t+1) visible
    }
}

extern "C" void kernel_launch(void* const* d_in, const int* in_sizes, int n_in,
                              void* d_out, int out_size) {
    const float* history = (const float*)d_in[0];
    const float* W_ih    = (const float*)d_in[1];
    const float* W_hh    = (const float*)d_in[2];
    const float* b_ih    = (const float*)d_in[3];
    const float* b_hh    = (const float*)d_in[4];
    const float* h0      = (const float*)d_in[5];
    float* out = (float*)d_out;

    cudaFuncSetAttribute(gru_v13,
                         cudaFuncAttributeMaxDynamicSharedMemorySize, SMEM_BYTES);
    gru_v13<<<NCTA, NTHR, SMEM_BYTES>>>(history, W_ih, W_hh,
                                        b_ih, b_hh, h0, out);
}